// round 12
// baseline (speedup 1.0000x reference)
#include <cuda_runtime.h>
#include <cstdint>

#define NB   8
#define NA   25200
#define NC   80
#define NTOP 1000
#define NBINS 4096
#define CAP  6144
#define NTILE 32     // ceil(NTOP/32)
#define NPAIR 528    // NTILE*(NTILE+1)/2 upper-tri tiles
#define SST_CAP 192

#define CBLK  256    // threads == anchors per k_conf block
#define CF4   20     // float4 per anchor (80 floats)
#define PADF4 21     // padded float4 stride (336B) -> conflict-free LDS
#define CONF_SMEM (CBLK * PADF4 * 16)

#define GRID_WAIT()  asm volatile("griddepcontrol.wait;" ::: "memory")
#define GRID_TRIG()  asm volatile("griddepcontrol.launch_dependents;" ::: "memory")

// -------------------- scratch (device globals; no allocation) --------------------
__device__ unsigned long long g_selkey[NB * NA];   // (bits(1-masked)<<32) | (anchor<<7) | cls
__device__ int                g_hist[NB * NBINS];  // zero at load; mega re-zeroes each replay
__device__ float              g_topv[NB * NTOP];
__device__ float              g_clsf[NB * NTOP];
__device__ float4             g_tb[NB * NTOP];
__device__ float4             g_ob[NB * NTOP];
__device__ unsigned           g_maskbits[NB * NTOP * 32]; // lower-tri words stay 0 forever
__device__ unsigned           g_rowflag[NB * 32];
__device__ int                g_ready[NB];         // mega(b) done flag   (reset by nms elect)
__device__ int                g_cnt2[NB];          // iou completion count (reset by nms elect)

// -------------------- kernel 1: conf/argmax, thread-per-anchor via smem staging --------------------
__global__ __launch_bounds__(256) void k_conf(const float* __restrict__ scores) {
    extern __shared__ float4 ss[];                 // CBLK*PADF4 float4 = 86016 B
    const float4* s4 = (const float4*)scores;
    int t = threadIdx.x;
    int blockbase = blockIdx.x * CBLK;
    const int total = NB * NA;

#pragma unroll
    for (int i = 0; i < CF4; i += 5) {
        float4 v[5];
#pragma unroll
        for (int k = 0; k < 5; k++) {
            int g = (i + k) * CBLK + t;
            int anc = blockbase + g / CF4;
            v[k] = (anc < total) ? s4[(size_t)blockbase * CF4 + g]
                                 : make_float4(0.f, 0.f, 0.f, 0.f);
        }
#pragma unroll
        for (int k = 0; k < 5; k++) {
            int g = (i + k) * CBLK + t;
            ss[(g / CF4) * PADF4 + (g % CF4)] = v[k];
        }
    }
    __syncthreads();

    int anchor = blockbase + t;
    const float4* arow = ss + t * PADF4;
    unsigned long long best = 0;
#pragma unroll
    for (int q = 0; q < CF4; q++) {
        float4 w = arow[q];
        int c = 4 * q;
        unsigned long long k0 = ((unsigned long long)__float_as_uint(w.x) << 8) | (unsigned)(255 - c);
        unsigned long long k1 = ((unsigned long long)__float_as_uint(w.y) << 8) | (unsigned)(254 - c);
        unsigned long long k2 = ((unsigned long long)__float_as_uint(w.z) << 8) | (unsigned)(253 - c);
        unsigned long long k3 = ((unsigned long long)__float_as_uint(w.w) << 8) | (unsigned)(252 - c);
        unsigned long long m01 = k0 > k1 ? k0 : k1;
        unsigned long long m23 = k2 > k3 ? k2 : k3;
        unsigned long long mq  = m01 > m23 ? m01 : m23;
        if (mq > best) best = mq;
    }

    unsigned hidx = 0xFFFFFFFFu;
    if (anchor < total) {
        unsigned valbits = (unsigned)(best >> 8);
        int      cls     = 255 - (int)(best & 0xFFull);
        float conf = __uint_as_float(valbits);     // scores nonneg: uint order == float order
        float m    = (conf >= 0.5f) ? conf : -1.0f;
        float tv   = 1.0f - m;                     // exact (Sterbenz) for m in [0.5,1]
        unsigned tb = __float_as_uint(tv);
        int b = anchor / NA;
        int a = anchor - b * NA;
        g_selkey[anchor] = ((unsigned long long)tb << 32) | ((unsigned)(a << 7)) | (unsigned)cls;
        hidx = (unsigned)(b * NBINS) + (tb >> 20);
    }
    unsigned grp = __match_any_sync(0xffffffffu, hidx);
    int leader = __ffs(grp) - 1;
    if ((t & 31) == leader && hidx != 0xFFFFFFFFu)
        atomicAdd(&g_hist[hidx], __popc(grp));
    GRID_TRIG();
}

// -------------------- kernel 2: fused tail (mega block + 17 iou blocks + elected nms) --------------------
// dyn smem (words), per-phase disjoint regions:
//   iou : sob float4[1024] @0 (4096w) | sar float[1024] @4096 (1024w)
//   nms : sst 192*33 @5120 (6336w) | slist @11456 (1024w) | svalid @12480 | srem @12512 | scount @12544
//   mega: cand @0 (12288w) | pre @12288 | cnt @16384 | wsum @20480 | scal @20512
#define TW_SOB   0
#define TW_SAR   4096
#define TW_SST   5120
#define TW_LIST  11456
#define TW_VAL   12480
#define TW_REM   12512
#define TW_CNT   12544
#define MW_CAND  0
#define MW_PRE   12288
#define MW_CNT   16384
#define MW_WSUM  20480
#define MW_SCAL  20512
#define TAIL_SMEM_WORDS 20516
__global__ __launch_bounds__(1024) void k_tail(const float* __restrict__ boxes,
                                               float* __restrict__ out) {
    extern __shared__ unsigned sh[];
    int b = blockIdx.y;
    int t = threadIdx.x;

    GRID_WAIT();                               // k_conf's hist/selkey now visible

    if (blockIdx.x == 17) {
        // ================= MEGA (unchanged body) =================
        unsigned long long* cand = (unsigned long long*)(sh + MW_CAND);
        int* pre  = (int*)(sh + MW_PRE);
        int* cnt  = (int*)(sh + MW_CNT);
        int* wsum = (int*)(sh + MW_WSUM);
        int* scal = (int*)(sh + MW_SCAL);
        int lane = t & 31, wid = t >> 5;

        if (t < 32) g_rowflag[b * 32 + t] = 0;    // before iou blocks' atomicOr (gated by g_ready)

        int hb = b * NBINS + t * 4;
        int h0 = g_hist[hb + 0], h1 = g_hist[hb + 1], h2 = g_hist[hb + 2], h3 = g_hist[hb + 3];
        g_hist[hb + 0] = 0; g_hist[hb + 1] = 0; g_hist[hb + 2] = 0; g_hist[hb + 3] = 0;
        int local = h0 + h1 + h2 + h3;

        int v = local;
#pragma unroll
        for (int off = 1; off < 32; off <<= 1) {
            int n = __shfl_up_sync(0xffffffffu, v, off);
            if (lane >= off) v += n;
        }
        if (lane == 31) wsum[wid] = v;
        if (t == 0) scal[0] = 1024;
        __syncthreads();
        if (t < 32) {
            int s = wsum[t];
            int is = s;
#pragma unroll
            for (int off = 1; off < 32; off <<= 1) {
                int n = __shfl_up_sync(0xffffffffu, is, off);
                if (t >= off) is += n;
            }
            wsum[t] = is - s;
        }
        __syncthreads();
        int incl = v + wsum[wid];
        int excl = incl - local;
        pre[t * 4 + 0] = excl;
        pre[t * 4 + 1] = excl + h0;
        pre[t * 4 + 2] = excl + h0 + h1;
        pre[t * 4 + 3] = excl + h0 + h1 + h2;
        cnt[t * 4 + 0] = 0; cnt[t * 4 + 1] = 0; cnt[t * 4 + 2] = 0; cnt[t * 4 + 3] = 0;
        if (excl < NTOP && incl >= NTOP) atomicMin(&scal[0], t);
        __syncthreads();
        if (t == scal[0]) {
            int bin, mm;
            if      (excl + h0 >= NTOP)           { bin = t * 4 + 0; mm = excl + h0; }
            else if (excl + h0 + h1 >= NTOP)      { bin = t * 4 + 1; mm = excl + h0 + h1; }
            else if (excl + h0 + h1 + h2 >= NTOP) { bin = t * 4 + 2; mm = excl + h0 + h1 + h2; }
            else                                  { bin = t * 4 + 3; mm = excl + local; }
            scal[1] = bin; scal[2] = mm;
        }
        __syncthreads();
        int chosen = scal[1];
        int m = scal[2]; if (m > CAP) m = CAP;

        const ulonglong2* keys2 = (const ulonglong2*)(g_selkey + (size_t)b * NA);
        for (int i = t; i < NA / 2; i += 1024) {
            ulonglong2 kk = keys2[i];
            int bin0 = (int)(kk.x >> 52);
            if (bin0 <= chosen) {
                int pos = pre[bin0] + atomicAdd(&cnt[bin0], 1);
                if (pos < CAP) cand[pos] = kk.x;
            }
            int bin1 = (int)(kk.y >> 52);
            if (bin1 <= chosen) {
                int pos = pre[bin1] + atomicAdd(&cnt[bin1], 1);
                if (pos < CAP) cand[pos] = kk.y;
            }
        }
        __syncthreads();

        const float4* bx4 = (const float4*)boxes;
        for (int e = t; e < m; e += 1024) {
            unsigned long long ke = cand[e];
            int bin = (int)(ke >> 52);
            int start = pre[bin];
            int end   = start + cnt[bin]; if (end > m) end = m;
            int rank  = start;
            for (int j = start; j < end; j++) rank += (cand[j] < ke) ? 1 : 0;
            if (rank < NTOP) {
                int a   = (int)((unsigned)(ke & 0xFFFFFFFFull) >> 7);
                int cls = (int)(ke & 127ull);
                float tt = __uint_as_float((unsigned)(ke >> 32));
                float vv = 1.0f - tt;                // bit-exact reconstruction of masked conf
                float cf = (float)cls;
                float4 bb = bx4[b * NA + a];
                int o = b * NTOP + rank;
                g_topv[o] = vv;
                g_clsf[o] = cf;
                g_tb[o]   = bb;
                float off = cf * 4096.0f;
                g_ob[o]   = make_float4(bb.x + off, bb.y + off, bb.z + off, bb.w + off);
            }
        }
        __threadfence();                        // release
        __syncthreads();
        if (t == 0) atomicExch(&g_ready[b], 1);
        return;
    }

    // ================= IOU blocks (x in [0,16], 32 warps = 32 tiles each) =================
    float4*   sob    = (float4*)(sh + TW_SOB);
    float*    sar    = (float*)(sh + TW_SAR);
    unsigned* sst    = sh + TW_SST;
    int*      slist  = (int*)(sh + TW_LIST);
    unsigned* svalid = sh + TW_VAL;
    unsigned* srem   = sh + TW_REM;
    int*      scount = (int*)(sh + TW_CNT);
    __shared__ int s_elect;

    if (t == 0) {
        while (atomicAdd(&g_ready[b], 0) == 0) __nanosleep(64);
    }
    __syncthreads();
    __threadfence();                            // acquire: mega's g_ob/rowflag visible

    for (int i = t; i < NTILE * 32; i += 1024) {
        float4 q = (i < NTOP) ? g_ob[b * NTOP + i] : make_float4(0.f, 0.f, 0.f, 0.f);
        sob[i] = q;
        sar[i] = (q.z - q.x) * (q.w - q.y);
    }
    __syncthreads();

    {
        int w = t >> 5, l = t & 31;
        int s = blockIdx.x * 32 + w;            // tile id
        if (s < NPAIR) {
            int TI = 0, rem = s;
            while (rem >= NTILE - TI) { rem -= NTILE - TI; TI++; }
            int TJ = TI + rem;

            int j = TJ * 32 + l;
            float4 bj   = sob[j];
            float areaj = sar[j];
            unsigned myword = 0;

#pragma unroll 1
            for (int ii = 0; ii < 32; ii++) {
                int i = TI * 32 + ii;
                float4 bi = sob[i];
                float xx1 = fmaxf(bi.x, bj.x);
                float yy1 = fmaxf(bi.y, bj.y);
                float xx2 = fminf(bi.z, bj.z);
                float yy2 = fminf(bi.w, bj.w);
                float iw = fmaxf(xx2 - xx1, 0.0f);
                float ih = fmaxf(yy2 - yy1, 0.0f);
                bool candp = (iw > 0.0f) && (ih > 0.0f) && (j > i) && (j < NTOP) && (i < NTOP);
                unsigned any = __ballot_sync(0xffffffffu, candp);
                unsigned word = 0;
                if (any) {
                    float inter = iw * ih;
                    float u = sar[i] + areaj - inter + 1e-7f;
                    bool sup = candp && ((inter / u) > 0.6f);   // exact div: match reference
                    word = __ballot_sync(0xffffffffu, sup);
                }
                if (l == ii) myword = word;
            }

            int i_row = TI * 32 + l;
            bool valid_row = (i_row < NTOP);
            if (valid_row) g_maskbits[((size_t)b * NTOP + i_row) * 32 + TJ] = myword;
            unsigned fl = __ballot_sync(0xffffffffu, (myword != 0) && valid_row);
            if (l == 0 && fl) atomicOr(&g_rowflag[b * 32 + TI], fl);
        }
    }

    // ---------- completion: 17th block of batch b runs NMS ----------
    __threadfence();
    __syncthreads();
    if (t == 0) {
        int old = atomicAdd(&g_cnt2[b], 1);
        s_elect = (old == 16);
    }
    __syncthreads();
    if (!s_elect) return;
    __threadfence();                            // acquire: all iou blocks' maskbits/rowflag visible

    // ================= NMS (validated body; SST cap + global fallback) =================
    float  v  = (t < NTOP) ? g_topv[b * NTOP + t] : -1.0f;
    float4 bb = make_float4(0.f, 0.f, 0.f, 0.f);
    float  cf = 0.0f;
    if (t < NTOP) { bb = g_tb[b * NTOP + t]; cf = g_clsf[b * NTOP + t]; }

    unsigned wd = __ballot_sync(0xffffffffu, v >= 0.5f);
    if ((t & 31) == 0) svalid[t >> 5] = wd;

    if (t < 32) {
        int l = t;
        unsigned flag = g_rowflag[b * 32 + l];
        int c = __popc(flag);
        int pr = c;
#pragma unroll
        for (int off = 1; off < 32; off <<= 1) {
            int n = __shfl_up_sync(0xffffffffu, pr, off);
            if (l >= off) pr += n;
        }
        int base = pr - c;
        int total = __shfl_sync(0xffffffffu, pr, 31);
        unsigned f = flag;
        int p = base;
        while (f) {
            int ii = __ffs(f) - 1; f &= f - 1;
            slist[p++] = l * 32 + ii;
        }
        if (l == 0) scount[0] = total;
    }
    __syncthreads();

    int S = scount[0];
    int Sc = S < SST_CAP ? S : SST_CAP;
    for (int idx = t; idx < Sc * 32; idx += 1024) {
        int r = idx >> 5, ww = idx & 31;
        sst[r * 33 + ww] = g_maskbits[((size_t)b * NTOP + slist[r]) * 32 + ww];
    }
    __syncthreads();

    if (t < 32) {
        int l = t;
        unsigned removed_l = 0;
        for (int s = 0; s < S; s++) {
            int i = slist[s];
            unsigned rowword = (s < SST_CAP) ? sst[s * 33 + l]
                                             : g_maskbits[((size_t)b * NTOP + i) * 32 + l];
            int g = i >> 5, ii = i & 31;
            unsigned rw = __shfl_sync(0xffffffffu, removed_l, g);
            bool alive = ((svalid[g] >> ii) & 1u) && !((rw >> ii) & 1u);
            if (alive) removed_l |= rowword;
        }
        srem[l] = removed_l;
    }
    __syncthreads();

    if (t < NTOP) {
        bool keep = (v >= 0.5f) && !((srem[t >> 5] >> (t & 31)) & 1u);
        float fk = keep ? 1.0f : 0.0f;
        int o = b * NTOP + t;
        float4 o0 = make_float4(v * fk, bb.x * fk, bb.y * fk, bb.z * fk);
        float4 o1 = make_float4(bb.w * fk, (float)b * fk, cf * fk, 0.0f);
        ((float4*)out)[o * 2 + 0] = o0;
        ((float4*)out)[o * 2 + 1] = o1;
    }

    // reset per-batch protocol state for the next replay (only elect block touches)
    if (t == 0) { g_cnt2[b] = 0; g_ready[b] = 0; }
}

// -------------------- launch: 2 PDL-chained nodes, allocation-free --------------------
static void launch_pdl(const void* func, dim3 grid, dim3 block, size_t smem,
                       void** args, bool dependent) {
    cudaLaunchConfig_t cfg = {};
    cfg.gridDim = grid;
    cfg.blockDim = block;
    cfg.dynamicSmemBytes = smem;
    cfg.stream = 0;
    cudaLaunchAttribute attr[1];
    if (dependent) {
        attr[0].id = cudaLaunchAttributeProgrammaticStreamSerialization;
        attr[0].val.programmaticStreamSerializationAllowed = 1;
        cfg.attrs = attr;
        cfg.numAttrs = 1;
    }
    cudaLaunchKernelExC(&cfg, func, args);
}

extern "C" void kernel_launch(void* const* d_in, const int* in_sizes, int n_in,
                              void* d_out, int out_size) {
    const float* boxes  = (const float*)d_in[0];
    const float* scores = (const float*)d_in[1];
    if (n_in >= 2 && in_sizes[0] > in_sizes[1]) {
        const float* tmp = boxes; boxes = scores; scores = tmp;
    }
    float* out = (float*)d_out;

    cudaFuncSetAttribute(k_conf, cudaFuncAttributeMaxDynamicSharedMemorySize, CONF_SMEM);
    cudaFuncSetAttribute(k_tail, cudaFuncAttributeMaxDynamicSharedMemorySize,
                         TAIL_SMEM_WORDS * 4);

    void* a_conf[] = { (void*)&scores };
    void* a_tail[] = { (void*)&boxes, (void*)&out };

    int conf_grid = (NB * NA + CBLK - 1) / CBLK;   // 788
    launch_pdl((const void*)k_conf, dim3(conf_grid), dim3(CBLK), CONF_SMEM, a_conf, false);
    launch_pdl((const void*)k_tail, dim3(18, NB), dim3(1024), TAIL_SMEM_WORDS * 4, a_tail, true);
    (void)out_size;
}

// round 13
// speedup vs baseline: 1.0576x; 1.0576x over previous
#include <cuda_runtime.h>
#include <cstdint>

#define NB   8
#define NA   25200
#define NC   80
#define NTOP 1000
#define NBINS 4096
#define CAP  6144
#define PAIRCAP 2048

#define CBLK  256    // threads == anchors per k_conf block
#define CF4   20     // float4 per anchor (80 floats)
#define PADF4 21     // padded float4 stride (336B) -> conflict-free LDS
#define CONF_SMEM (CBLK * PADF4 * 16)

#define GRID_WAIT()  asm volatile("griddepcontrol.wait;" ::: "memory")
#define GRID_TRIG()  asm volatile("griddepcontrol.launch_dependents;" ::: "memory")

// -------------------- scratch (device globals; no allocation) --------------------
__device__ unsigned long long g_selkey[NB * NA];   // (bits(1-masked)<<32) | (anchor<<7) | cls
__device__ int                g_hist[NB * NBINS];  // zero at load; k_tail re-zeroes each replay

// -------------------- kernel 1: conf/argmax, thread-per-anchor via smem staging --------------------
__global__ __launch_bounds__(256) void k_conf(const float* __restrict__ scores) {
    extern __shared__ float4 ss[];                 // CBLK*PADF4 float4 = 86016 B
    const float4* s4 = (const float4*)scores;
    int t = threadIdx.x;
    int blockbase = blockIdx.x * CBLK;
    const int total = NB * NA;

#pragma unroll
    for (int i = 0; i < CF4; i += 5) {
        float4 v[5];
#pragma unroll
        for (int k = 0; k < 5; k++) {
            int g = (i + k) * CBLK + t;
            int anc = blockbase + g / CF4;
            v[k] = (anc < total) ? s4[(size_t)blockbase * CF4 + g]
                                 : make_float4(0.f, 0.f, 0.f, 0.f);
        }
#pragma unroll
        for (int k = 0; k < 5; k++) {
            int g = (i + k) * CBLK + t;
            ss[(g / CF4) * PADF4 + (g % CF4)] = v[k];
        }
    }
    __syncthreads();

    int anchor = blockbase + t;
    const float4* arow = ss + t * PADF4;
    unsigned long long best = 0;
#pragma unroll
    for (int q = 0; q < CF4; q++) {
        float4 w = arow[q];
        int c = 4 * q;
        unsigned long long k0 = ((unsigned long long)__float_as_uint(w.x) << 8) | (unsigned)(255 - c);
        unsigned long long k1 = ((unsigned long long)__float_as_uint(w.y) << 8) | (unsigned)(254 - c);
        unsigned long long k2 = ((unsigned long long)__float_as_uint(w.z) << 8) | (unsigned)(253 - c);
        unsigned long long k3 = ((unsigned long long)__float_as_uint(w.w) << 8) | (unsigned)(252 - c);
        unsigned long long m01 = k0 > k1 ? k0 : k1;
        unsigned long long m23 = k2 > k3 ? k2 : k3;
        unsigned long long mq  = m01 > m23 ? m01 : m23;
        if (mq > best) best = mq;
    }

    unsigned hidx = 0xFFFFFFFFu;
    if (anchor < total) {
        unsigned valbits = (unsigned)(best >> 8);
        int      cls     = 255 - (int)(best & 0xFFull);
        float conf = __uint_as_float(valbits);     // scores nonneg: uint order == float order
        float m    = (conf >= 0.5f) ? conf : -1.0f;
        float tv   = 1.0f - m;                     // exact (Sterbenz) for m in [0.5,1]
        unsigned tb = __float_as_uint(tv);
        int b = anchor / NA;
        int a = anchor - b * NA;
        g_selkey[anchor] = ((unsigned long long)tb << 32) | ((unsigned)(a << 7)) | (unsigned)cls;
        hidx = (unsigned)(b * NBINS) + (tb >> 20);
    }
    unsigned grp = __match_any_sync(0xffffffffu, hidx);
    int leader = __ffs(grp) - 1;
    if ((t & 31) == leader && hidx != 0xFFFFFFFFu)
        atomicAdd(&g_hist[hidx], __popc(grp));
    GRID_TRIG();
}

// -------------------- kernel 2: full tail, ONE block per batch --------------------
// smem layout (words):
#define MW_CAND  0       // ull[CAP]            12288
#define MW_PRE   12288   // int[4096]
#define MW_CNT   16384   // int[4096]
#define MW_WSUM  20480   // int[32]
#define MW_SCAL  20512   // int[4]
#define W_SV     20516   // float[1024]
#define W_SCL    21540   // int[1024]
#define W_STB    22564   // float4[1024] (16B aligned: 22564%4==0)
#define W_SOB    26660   // float4[1024]
#define W_BCNT   30756   // int[128]
#define W_BPRE   30884   // int[128]
#define W_BCUR   31012   // int[128]
#define W_BMEM   31140   // int[1024]
#define W_PAIRS  32164   // int[PAIRCAP]
#define W_SPAIRS 34212   // int[PAIRCAP]
#define W_SKEEP  36260   // unsigned[32]
#define W_NP     36292   // int[1]
#define TAIL_SMEM_WORDS 36296
__global__ __launch_bounds__(1024) void k_tail(const float* __restrict__ boxes,
                                               float* __restrict__ out) {
    extern __shared__ unsigned sh[];
    unsigned long long* cand = (unsigned long long*)(sh + MW_CAND);
    int*      pre   = (int*)(sh + MW_PRE);
    int*      cnt   = (int*)(sh + MW_CNT);
    int*      wsum  = (int*)(sh + MW_WSUM);
    int*      scal  = (int*)(sh + MW_SCAL);
    float*    sv    = (float*)(sh + W_SV);
    int*      scl   = (int*)(sh + W_SCL);
    float4*   stb   = (float4*)(sh + W_STB);
    float4*   sob   = (float4*)(sh + W_SOB);
    int*      bcnt  = (int*)(sh + W_BCNT);
    int*      bpre  = (int*)(sh + W_BPRE);
    int*      bcur  = (int*)(sh + W_BCUR);
    int*      bmem  = (int*)(sh + W_BMEM);
    int*      pairs = (int*)(sh + W_PAIRS);
    int*      spairs= (int*)(sh + W_SPAIRS);
    unsigned* skeep = sh + W_SKEEP;
    int*      np    = (int*)(sh + W_NP);

    int b = blockIdx.x, t = threadIdx.x;
    int lane = t & 31, wid = t >> 5;

    GRID_WAIT();                               // k_conf's hist/selkey now visible

    // ---- init rank-array defaults + bucket counters ----
    sv[t]  = -1.0f;
    scl[t] = 127;
    stb[t] = make_float4(0.f, 0.f, 0.f, 0.f);
    sob[t] = make_float4(0.f, 0.f, 0.f, 0.f);
    if (t < 128) { bcnt[t] = 0; bcur[t] = 0; }
    if (t == 0) np[0] = 0;

    // ---- mega: decide boundary bin ----
    int hb = b * NBINS + t * 4;
    int h0 = g_hist[hb + 0], h1 = g_hist[hb + 1], h2 = g_hist[hb + 2], h3 = g_hist[hb + 3];
    g_hist[hb + 0] = 0; g_hist[hb + 1] = 0; g_hist[hb + 2] = 0; g_hist[hb + 3] = 0;
    int local = h0 + h1 + h2 + h3;

    int v = local;
#pragma unroll
    for (int off = 1; off < 32; off <<= 1) {
        int n = __shfl_up_sync(0xffffffffu, v, off);
        if (lane >= off) v += n;
    }
    if (lane == 31) wsum[wid] = v;
    if (t == 0) scal[0] = 1024;
    __syncthreads();
    if (t < 32) {
        int s = wsum[t];
        int is = s;
#pragma unroll
        for (int off = 1; off < 32; off <<= 1) {
            int n = __shfl_up_sync(0xffffffffu, is, off);
            if (t >= off) is += n;
        }
        wsum[t] = is - s;
    }
    __syncthreads();
    int incl = v + wsum[wid];
    int excl = incl - local;
    pre[t * 4 + 0] = excl;
    pre[t * 4 + 1] = excl + h0;
    pre[t * 4 + 2] = excl + h0 + h1;
    pre[t * 4 + 3] = excl + h0 + h1 + h2;
    cnt[t * 4 + 0] = 0; cnt[t * 4 + 1] = 0; cnt[t * 4 + 2] = 0; cnt[t * 4 + 3] = 0;
    if (excl < NTOP && incl >= NTOP) atomicMin(&scal[0], t);
    __syncthreads();
    if (t == scal[0]) {
        int bin, mm;
        if      (excl + h0 >= NTOP)           { bin = t * 4 + 0; mm = excl + h0; }
        else if (excl + h0 + h1 >= NTOP)      { bin = t * 4 + 1; mm = excl + h0 + h1; }
        else if (excl + h0 + h1 + h2 >= NTOP) { bin = t * 4 + 2; mm = excl + h0 + h1 + h2; }
        else                                  { bin = t * 4 + 3; mm = excl + local; }
        scal[1] = bin; scal[2] = mm;
    }
    __syncthreads();
    int chosen = scal[1];
    int m = scal[2]; if (m > CAP) m = CAP;

    // ---- mega: bin-grouped compaction ----
    const ulonglong2* keys2 = (const ulonglong2*)(g_selkey + (size_t)b * NA);
    for (int i = t; i < NA / 2; i += 1024) {
        ulonglong2 kk = keys2[i];
        int bin0 = (int)(kk.x >> 52);
        if (bin0 <= chosen) {
            int pos = pre[bin0] + atomicAdd(&cnt[bin0], 1);
            if (pos < CAP) cand[pos] = kk.x;
        }
        int bin1 = (int)(kk.y >> 52);
        if (bin1 <= chosen) {
            int pos = pre[bin1] + atomicAdd(&cnt[bin1], 1);
            if (pos < CAP) cand[pos] = kk.y;
        }
    }
    __syncthreads();

    // ---- mega: per-bin rank + gather into smem ----
    const float4* bx4 = (const float4*)boxes;
    for (int e = t; e < m; e += 1024) {
        unsigned long long ke = cand[e];
        int bin = (int)(ke >> 52);
        int start = pre[bin];
        int end   = start + cnt[bin]; if (end > m) end = m;
        int rank  = start;
        for (int j = start; j < end; j++) rank += (cand[j] < ke) ? 1 : 0;
        if (rank < NTOP) {
            int a   = (int)((unsigned)(ke & 0xFFFFFFFFull) >> 7);
            int cls = (int)(ke & 127ull);
            float tt = __uint_as_float((unsigned)(ke >> 32));
            float vv = 1.0f - tt;                // bit-exact reconstruction of masked conf
            float cf = (float)cls;
            float4 bb = bx4[b * NA + a];
            sv[rank]  = vv;
            scl[rank] = cls;
            stb[rank] = bb;
            float off = cf * 4096.0f;            // exact (int*pow2)
            sob[rank] = make_float4(bb.x + off, bb.y + off, bb.z + off, bb.w + off);
        }
    }
    __syncthreads();

    // ---- class buckets: count, prefix, scatter ----
    if (t < NTOP) atomicAdd(&bcnt[scl[t]], 1);
    __syncthreads();
    if (t < 32) {
        int s0 = bcnt[t * 4 + 0], s1 = bcnt[t * 4 + 1], s2 = bcnt[t * 4 + 2], s3 = bcnt[t * 4 + 3];
        int loc = s0 + s1 + s2 + s3;
        int is = loc;
#pragma unroll
        for (int off = 1; off < 32; off <<= 1) {
            int n = __shfl_up_sync(0xffffffffu, is, off);
            if (t >= off) is += n;
        }
        int base = is - loc;
        bpre[t * 4 + 0] = base;
        bpre[t * 4 + 1] = base + s0;
        bpre[t * 4 + 2] = base + s0 + s1;
        bpre[t * 4 + 3] = base + s0 + s1 + s2;
    }
    __syncthreads();
    if (t < NTOP) {
        int c = scl[t];
        bmem[bpre[c] + atomicAdd(&bcur[c], 1)] = t;   // bucket order irrelevant
    }
    __syncthreads();

    // ---- within-class IoU pairs only (cross-class inter == 0 exactly: offsets >= 4096 apart) ----
    {
#pragma unroll 1
        for (int cc = 0; cc < 4; cc++) {
            int c = wid * 4 + cc;
            int n = bcnt[c];
            int base = bpre[c];
            int npair = n * (n - 1) / 2;
            for (int p = lane; p < npair; p += 32) {
                // decode triangular index -> (a, b), a < b
                int a = 0, rem = p;
                while (rem >= n - 1 - a) { rem -= n - 1 - a; a++; }
                int bb2 = a + 1 + rem;
                int ra = bmem[base + a], rb = bmem[base + bb2];
                int i = ra < rb ? ra : rb;
                int j = ra < rb ? rb : ra;
                float4 bi = sob[i];
                float4 bj = sob[j];
                float xx1 = fmaxf(bi.x, bj.x);
                float yy1 = fmaxf(bi.y, bj.y);
                float xx2 = fminf(bi.z, bj.z);
                float yy2 = fminf(bi.w, bj.w);
                float iw = fmaxf(xx2 - xx1, 0.0f);
                float ih = fmaxf(yy2 - yy1, 0.0f);
                float inter = iw * ih;
                float areai = (bi.z - bi.x) * (bi.w - bi.y);
                float areaj = (bj.z - bj.x) * (bj.w - bj.y);
                float u = areai + areaj - inter + 1e-7f;
                if ((inter / u) > 0.6f) {                       // exact div: match reference
                    int pos = atomicAdd(np, 1);
                    if (pos < PAIRCAP) pairs[pos] = (i << 10) | j;
                }
            }
        }
    }
    __syncthreads();

    // ---- rank-sort pairs by (i,j) ----
    int P = np[0]; if (P > PAIRCAP) P = PAIRCAP;
    for (int k = t; k < P; k += 1024) {
        int val = pairs[k];
        int rk = 0;
        for (int q = 0; q < P; q++) rk += (pairs[q] < val) ? 1 : 0;   // values unique
        spairs[rk] = val;
    }
    // keep-bit init
    {
        float vv = sv[t];
        unsigned wd = __ballot_sync(0xffffffffu, vv >= 0.5f && t < NTOP);
        if (lane == 0) skeep[wid] = wd;
    }
    __syncthreads();

    // ---- serial greedy over sorted pairs (ascending i => keep[i] final when reached) ----
    if (t == 0) {
        for (int k = 0; k < P; k++) {
            int v2 = spairs[k];
            int i = v2 >> 10, j = v2 & 1023;
            if ((skeep[i >> 5] >> (i & 31)) & 1u)
                skeep[j >> 5] &= ~(1u << (j & 31));
        }
    }
    __syncthreads();

    // ---- output ----
    if (t < NTOP) {
        bool keep = (skeep[t >> 5] >> (t & 31)) & 1u;
        float vv = sv[t];
        float fk = keep ? 1.0f : 0.0f;
        float4 bb = stb[t];
        float cf = (float)scl[t];
        int o = b * NTOP + t;
        float4 o0 = make_float4(vv * fk, bb.x * fk, bb.y * fk, bb.z * fk);
        float4 o1 = make_float4(bb.w * fk, (float)b * fk, cf * fk, 0.0f);
        ((float4*)out)[o * 2 + 0] = o0;
        ((float4*)out)[o * 2 + 1] = o1;
    }
}

// -------------------- launch: 2 PDL-chained nodes, allocation-free --------------------
static void launch_pdl(const void* func, dim3 grid, dim3 block, size_t smem,
                       void** args, bool dependent) {
    cudaLaunchConfig_t cfg = {};
    cfg.gridDim = grid;
    cfg.blockDim = block;
    cfg.dynamicSmemBytes = smem;
    cfg.stream = 0;
    cudaLaunchAttribute attr[1];
    if (dependent) {
        attr[0].id = cudaLaunchAttributeProgrammaticStreamSerialization;
        attr[0].val.programmaticStreamSerializationAllowed = 1;
        cfg.attrs = attr;
        cfg.numAttrs = 1;
    }
    cudaLaunchKernelExC(&cfg, func, args);
}

extern "C" void kernel_launch(void* const* d_in, const int* in_sizes, int n_in,
                              void* d_out, int out_size) {
    const float* boxes  = (const float*)d_in[0];
    const float* scores = (const float*)d_in[1];
    if (n_in >= 2 && in_sizes[0] > in_sizes[1]) {
        const float* tmp = boxes; boxes = scores; scores = tmp;
    }
    float* out = (float*)d_out;

    cudaFuncSetAttribute(k_conf, cudaFuncAttributeMaxDynamicSharedMemorySize, CONF_SMEM);
    cudaFuncSetAttribute(k_tail, cudaFuncAttributeMaxDynamicSharedMemorySize,
                         TAIL_SMEM_WORDS * 4);

    void* a_conf[] = { (void*)&scores };
    void* a_tail[] = { (void*)&boxes, (void*)&out };

    int conf_grid = (NB * NA + CBLK - 1) / CBLK;   // 788
    launch_pdl((const void*)k_conf, dim3(conf_grid), dim3(CBLK), CONF_SMEM, a_conf, false);
    launch_pdl((const void*)k_tail, dim3(NB), dim3(1024), TAIL_SMEM_WORDS * 4, a_tail, true);
    (void)out_size;
}

// round 14
// speedup vs baseline: 1.1165x; 1.0557x over previous
#include <cuda_runtime.h>
#include <cstdint>

#define NB   8
#define NA   25200
#define NC   80
#define NTOP 1000
#define NBINS 4096
#define CAP  6144
#define PAIRCAP 2048

#define CBLK  256    // threads == anchors per k_conf block
#define CF4   20     // float4 per anchor (80 floats)
#define PADF4 21     // padded float4 stride (336B) -> conflict-free LDS
#define CONF_SMEM (CBLK * PADF4 * 16)

#define GRID_WAIT()  asm volatile("griddepcontrol.wait;" ::: "memory")
#define GRID_TRIG()  asm volatile("griddepcontrol.launch_dependents;" ::: "memory")

// -------------------- scratch (device globals; no allocation) --------------------
__device__ unsigned long long g_selkey[NB * NA];   // (bits(1-masked)<<32) | (anchor<<7) | cls
__device__ int                g_hist[NB * NBINS];  // zero at load; k_tail re-zeroes each replay

// -------------------- kernel 1: conf/argmax, thread-per-anchor via smem staging --------------------
__global__ __launch_bounds__(256) void k_conf(const float* __restrict__ scores) {
    extern __shared__ float4 ss[];                 // CBLK*PADF4 float4 = 86016 B
    const float4* s4 = (const float4*)scores;
    int t = threadIdx.x;
    int blockbase = blockIdx.x * CBLK;
    const int total = NB * NA;

#pragma unroll
    for (int i = 0; i < CF4; i += 5) {
        float4 v[5];
#pragma unroll
        for (int k = 0; k < 5; k++) {
            int g = (i + k) * CBLK + t;
            int anc = blockbase + g / CF4;
            v[k] = (anc < total) ? s4[(size_t)blockbase * CF4 + g]
                                 : make_float4(0.f, 0.f, 0.f, 0.f);
        }
#pragma unroll
        for (int k = 0; k < 5; k++) {
            int g = (i + k) * CBLK + t;
            ss[(g / CF4) * PADF4 + (g % CF4)] = v[k];
        }
    }
    __syncthreads();

    int anchor = blockbase + t;
    const float4* arow = ss + t * PADF4;
    unsigned long long best = 0;
#pragma unroll
    for (int q = 0; q < CF4; q++) {
        float4 w = arow[q];
        int c = 4 * q;
        unsigned long long k0 = ((unsigned long long)__float_as_uint(w.x) << 8) | (unsigned)(255 - c);
        unsigned long long k1 = ((unsigned long long)__float_as_uint(w.y) << 8) | (unsigned)(254 - c);
        unsigned long long k2 = ((unsigned long long)__float_as_uint(w.z) << 8) | (unsigned)(253 - c);
        unsigned long long k3 = ((unsigned long long)__float_as_uint(w.w) << 8) | (unsigned)(252 - c);
        unsigned long long m01 = k0 > k1 ? k0 : k1;
        unsigned long long m23 = k2 > k3 ? k2 : k3;
        unsigned long long mq  = m01 > m23 ? m01 : m23;
        if (mq > best) best = mq;
    }

    unsigned hidx = 0xFFFFFFFFu;
    if (anchor < total) {
        unsigned valbits = (unsigned)(best >> 8);
        int      cls     = 255 - (int)(best & 0xFFull);
        float conf = __uint_as_float(valbits);     // scores nonneg: uint order == float order
        float m    = (conf >= 0.5f) ? conf : -1.0f;
        float tv   = 1.0f - m;                     // exact (Sterbenz) for m in [0.5,1]
        unsigned tb = __float_as_uint(tv);
        int b = anchor / NA;
        int a = anchor - b * NA;
        g_selkey[anchor] = ((unsigned long long)tb << 32) | ((unsigned)(a << 7)) | (unsigned)cls;
        hidx = (unsigned)(b * NBINS) + (tb >> 20);
    }
    unsigned grp = __match_any_sync(0xffffffffu, hidx);
    int leader = __ffs(grp) - 1;
    if ((t & 31) == leader && hidx != 0xFFFFFFFFu)
        atomicAdd(&g_hist[hidx], __popc(grp));
    GRID_TRIG();
}

// -------------------- kernel 2: full tail, ONE working block per batch (grid padded to 148) --------------------
// smem layout (words):
#define MW_CAND  0       // ull[CAP]            12288
#define MW_PRE   12288   // int[4096]
#define MW_CNT   16384   // int[4096]
#define MW_WSUM  20480   // int[32]
#define MW_SCAL  20512   // int[4]
#define W_SV     20516   // float[1024]
#define W_SCL    21540   // int[1024]
#define W_STB    22564   // float4[1024]
#define W_SOB    26660   // float4[1024]
#define W_BCNT   30756   // int[128]
#define W_BPRE   30884   // int[128]
#define W_BCUR   31012   // int[128]
#define W_BMEM   31140   // int[1024]
#define W_PAIRS  32164   // int[PAIRCAP]
#define W_SPAIRS 34212   // int[PAIRCAP]
#define W_SKEEP  36260   // unsigned[32]
#define W_NP     36292   // int[1]
#define TAIL_SMEM_WORDS 36296
__global__ __launch_bounds__(1024) void k_tail(const float* __restrict__ boxes,
                                               float* __restrict__ out) {
    // grid padded to >=148 to dodge low-grid SM issue throttle; extra blocks exit
    if (blockIdx.x >= NB) return;

    extern __shared__ unsigned sh[];
    unsigned long long* cand = (unsigned long long*)(sh + MW_CAND);
    int*      pre   = (int*)(sh + MW_PRE);
    int*      cnt   = (int*)(sh + MW_CNT);
    int*      wsum  = (int*)(sh + MW_WSUM);
    int*      scal  = (int*)(sh + MW_SCAL);
    float*    sv    = (float*)(sh + W_SV);
    int*      scl   = (int*)(sh + W_SCL);
    float4*   stb   = (float4*)(sh + W_STB);
    float4*   sob   = (float4*)(sh + W_SOB);
    int*      bcnt  = (int*)(sh + W_BCNT);
    int*      bpre  = (int*)(sh + W_BPRE);
    int*      bcur  = (int*)(sh + W_BCUR);
    int*      bmem  = (int*)(sh + W_BMEM);
    int*      pairs = (int*)(sh + W_PAIRS);
    int*      spairs= (int*)(sh + W_SPAIRS);
    unsigned* skeep = sh + W_SKEEP;
    int*      np    = (int*)(sh + W_NP);

    int b = blockIdx.x, t = threadIdx.x;
    int lane = t & 31, wid = t >> 5;

    GRID_WAIT();                               // k_conf's hist/selkey now visible

    // ---- init rank-array defaults + bucket counters ----
    sv[t]  = -1.0f;
    scl[t] = 127;
    stb[t] = make_float4(0.f, 0.f, 0.f, 0.f);
    sob[t] = make_float4(0.f, 0.f, 0.f, 0.f);
    if (t < 128) { bcnt[t] = 0; bcur[t] = 0; }
    if (t == 0) np[0] = 0;

    // ---- mega: decide boundary bin ----
    int hb = b * NBINS + t * 4;
    int h0 = g_hist[hb + 0], h1 = g_hist[hb + 1], h2 = g_hist[hb + 2], h3 = g_hist[hb + 3];
    g_hist[hb + 0] = 0; g_hist[hb + 1] = 0; g_hist[hb + 2] = 0; g_hist[hb + 3] = 0;
    int local = h0 + h1 + h2 + h3;

    int v = local;
#pragma unroll
    for (int off = 1; off < 32; off <<= 1) {
        int n = __shfl_up_sync(0xffffffffu, v, off);
        if (lane >= off) v += n;
    }
    if (lane == 31) wsum[wid] = v;
    if (t == 0) scal[0] = 1024;
    __syncthreads();
    if (t < 32) {
        int s = wsum[t];
        int is = s;
#pragma unroll
        for (int off = 1; off < 32; off <<= 1) {
            int n = __shfl_up_sync(0xffffffffu, is, off);
            if (t >= off) is += n;
        }
        wsum[t] = is - s;
    }
    __syncthreads();
    int incl = v + wsum[wid];
    int excl = incl - local;
    pre[t * 4 + 0] = excl;
    pre[t * 4 + 1] = excl + h0;
    pre[t * 4 + 2] = excl + h0 + h1;
    pre[t * 4 + 3] = excl + h0 + h1 + h2;
    cnt[t * 4 + 0] = 0; cnt[t * 4 + 1] = 0; cnt[t * 4 + 2] = 0; cnt[t * 4 + 3] = 0;
    if (excl < NTOP && incl >= NTOP) atomicMin(&scal[0], t);
    __syncthreads();
    if (t == scal[0]) {
        int bin, mm;
        if      (excl + h0 >= NTOP)           { bin = t * 4 + 0; mm = excl + h0; }
        else if (excl + h0 + h1 >= NTOP)      { bin = t * 4 + 1; mm = excl + h0 + h1; }
        else if (excl + h0 + h1 + h2 >= NTOP) { bin = t * 4 + 2; mm = excl + h0 + h1 + h2; }
        else                                  { bin = t * 4 + 3; mm = excl + local; }
        scal[1] = bin; scal[2] = mm;
    }
    __syncthreads();
    int chosen = scal[1];
    int m = scal[2]; if (m > CAP) m = CAP;

    // ---- mega: bin-grouped compaction, MLP=4 front-batched rounds ----
    const ulonglong2* keys2 = (const ulonglong2*)(g_selkey + (size_t)b * NA);
    for (int base = 0; base < 12288; base += 4096) {          // 3 rounds x 4 loads
        ulonglong2 kk[4];
#pragma unroll
        for (int r = 0; r < 4; r++) kk[r] = keys2[base + r * 1024 + t];
#pragma unroll
        for (int r = 0; r < 4; r++) {
            int bin0 = (int)(kk[r].x >> 52);
            if (bin0 <= chosen) {
                int pos = pre[bin0] + atomicAdd(&cnt[bin0], 1);
                if (pos < CAP) cand[pos] = kk[r].x;
            }
            int bin1 = (int)(kk[r].y >> 52);
            if (bin1 <= chosen) {
                int pos = pre[bin1] + atomicAdd(&cnt[bin1], 1);
                if (pos < CAP) cand[pos] = kk[r].y;
            }
        }
    }
    if (t < (NA / 2 - 12288)) {                                // remainder 312
        ulonglong2 kk = keys2[12288 + t];
        int bin0 = (int)(kk.x >> 52);
        if (bin0 <= chosen) {
            int pos = pre[bin0] + atomicAdd(&cnt[bin0], 1);
            if (pos < CAP) cand[pos] = kk.x;
        }
        int bin1 = (int)(kk.y >> 52);
        if (bin1 <= chosen) {
            int pos = pre[bin1] + atomicAdd(&cnt[bin1], 1);
            if (pos < CAP) cand[pos] = kk.y;
        }
    }
    __syncthreads();

    // ---- mega: per-bin rank + gather into smem ----
    const float4* bx4 = (const float4*)boxes;
    for (int e = t; e < m; e += 1024) {
        unsigned long long ke = cand[e];
        int bin = (int)(ke >> 52);
        int start = pre[bin];
        int end   = start + cnt[bin]; if (end > m) end = m;
        int rank  = start;
        for (int j = start; j < end; j++) rank += (cand[j] < ke) ? 1 : 0;
        if (rank < NTOP) {
            int a   = (int)((unsigned)(ke & 0xFFFFFFFFull) >> 7);
            int cls = (int)(ke & 127ull);
            float tt = __uint_as_float((unsigned)(ke >> 32));
            float vv = 1.0f - tt;                // bit-exact reconstruction of masked conf
            float cf = (float)cls;
            float4 bb = bx4[b * NA + a];
            sv[rank]  = vv;
            scl[rank] = cls;
            stb[rank] = bb;
            float off = cf * 4096.0f;            // exact (int*pow2)
            sob[rank] = make_float4(bb.x + off, bb.y + off, bb.z + off, bb.w + off);
        }
    }
    __syncthreads();

    // ---- class buckets: count, prefix, scatter ----
    if (t < NTOP) atomicAdd(&bcnt[scl[t]], 1);
    __syncthreads();
    if (t < 32) {
        int s0 = bcnt[t * 4 + 0], s1 = bcnt[t * 4 + 1], s2 = bcnt[t * 4 + 2], s3 = bcnt[t * 4 + 3];
        int loc = s0 + s1 + s2 + s3;
        int is = loc;
#pragma unroll
        for (int off = 1; off < 32; off <<= 1) {
            int n = __shfl_up_sync(0xffffffffu, is, off);
            if (t >= off) is += n;
        }
        int base = is - loc;
        bpre[t * 4 + 0] = base;
        bpre[t * 4 + 1] = base + s0;
        bpre[t * 4 + 2] = base + s0 + s1;
        bpre[t * 4 + 3] = base + s0 + s1 + s2;
    }
    __syncthreads();
    if (t < NTOP) {
        int c = scl[t];
        bmem[bpre[c] + atomicAdd(&bcur[c], 1)] = t;   // bucket order irrelevant
    }
    __syncthreads();

    // ---- within-class IoU pairs only (cross-class inter == 0 exactly: offsets >= 4096 apart) ----
    {
#pragma unroll 1
        for (int cc = 0; cc < 4; cc++) {
            int c = wid * 4 + cc;
            int n = bcnt[c];
            int base = bpre[c];
            int npair = n * (n - 1) / 2;
            for (int p = lane; p < npair; p += 32) {
                int a = 0, rem = p;
                while (rem >= n - 1 - a) { rem -= n - 1 - a; a++; }
                int bb2 = a + 1 + rem;
                int ra = bmem[base + a], rb = bmem[base + bb2];
                int i = ra < rb ? ra : rb;
                int j = ra < rb ? rb : ra;
                float4 bi = sob[i];
                float4 bj = sob[j];
                float xx1 = fmaxf(bi.x, bj.x);
                float yy1 = fmaxf(bi.y, bj.y);
                float xx2 = fminf(bi.z, bj.z);
                float yy2 = fminf(bi.w, bj.w);
                float iw = fmaxf(xx2 - xx1, 0.0f);
                float ih = fmaxf(yy2 - yy1, 0.0f);
                float inter = iw * ih;
                float areai = (bi.z - bi.x) * (bi.w - bi.y);
                float areaj = (bj.z - bj.x) * (bj.w - bj.y);
                float u = areai + areaj - inter + 1e-7f;
                if ((inter / u) > 0.6f) {                       // exact div: match reference
                    int pos = atomicAdd(np, 1);
                    if (pos < PAIRCAP) pairs[pos] = (i << 10) | j;
                }
            }
        }
    }
    __syncthreads();

    // ---- rank-sort pairs by (i,j) ----
    int P = np[0]; if (P > PAIRCAP) P = PAIRCAP;
    for (int k = t; k < P; k += 1024) {
        int val = pairs[k];
        int rk = 0;
        for (int q = 0; q < P; q++) rk += (pairs[q] < val) ? 1 : 0;   // values unique
        spairs[rk] = val;
    }
    {
        float vv = sv[t];
        unsigned wd = __ballot_sync(0xffffffffu, vv >= 0.5f && t < NTOP);
        if (lane == 0) skeep[wid] = wd;
    }
    __syncthreads();

    // ---- serial greedy over sorted pairs (ascending i => keep[i] final when reached) ----
    if (t == 0) {
        for (int k = 0; k < P; k++) {
            int v2 = spairs[k];
            int i = v2 >> 10, j = v2 & 1023;
            if ((skeep[i >> 5] >> (i & 31)) & 1u)
                skeep[j >> 5] &= ~(1u << (j & 31));
        }
    }
    __syncthreads();

    // ---- output ----
    if (t < NTOP) {
        bool keep = (skeep[t >> 5] >> (t & 31)) & 1u;
        float vv = sv[t];
        float fk = keep ? 1.0f : 0.0f;
        float4 bb = stb[t];
        float cf = (float)scl[t];
        int o = b * NTOP + t;
        float4 o0 = make_float4(vv * fk, bb.x * fk, bb.y * fk, bb.z * fk);
        float4 o1 = make_float4(bb.w * fk, (float)b * fk, cf * fk, 0.0f);
        ((float4*)out)[o * 2 + 0] = o0;
        ((float4*)out)[o * 2 + 1] = o1;
    }
}

// -------------------- launch: 2 PDL-chained nodes, allocation-free --------------------
static void launch_pdl(const void* func, dim3 grid, dim3 block, size_t smem,
                       void** args, bool dependent) {
    cudaLaunchConfig_t cfg = {};
    cfg.gridDim = grid;
    cfg.blockDim = block;
    cfg.dynamicSmemBytes = smem;
    cfg.stream = 0;
    cudaLaunchAttribute attr[1];
    if (dependent) {
        attr[0].id = cudaLaunchAttributeProgrammaticStreamSerialization;
        attr[0].val.programmaticStreamSerializationAllowed = 1;
        cfg.attrs = attr;
        cfg.numAttrs = 1;
    }
    cudaLaunchKernelExC(&cfg, func, args);
}

extern "C" void kernel_launch(void* const* d_in, const int* in_sizes, int n_in,
                              void* d_out, int out_size) {
    const float* boxes  = (const float*)d_in[0];
    const float* scores = (const float*)d_in[1];
    if (n_in >= 2 && in_sizes[0] > in_sizes[1]) {
        const float* tmp = boxes; boxes = scores; scores = tmp;
    }
    float* out = (float*)d_out;

    cudaFuncSetAttribute(k_conf, cudaFuncAttributeMaxDynamicSharedMemorySize, CONF_SMEM);
    cudaFuncSetAttribute(k_tail, cudaFuncAttributeMaxDynamicSharedMemorySize,
                         TAIL_SMEM_WORDS * 4);

    void* a_conf[] = { (void*)&scores };
    void* a_tail[] = { (void*)&boxes, (void*)&out };

    int conf_grid = (NB * NA + CBLK - 1) / CBLK;   // 788
    launch_pdl((const void*)k_conf, dim3(conf_grid), dim3(CBLK), CONF_SMEM, a_conf, false);
    launch_pdl((const void*)k_tail, dim3(148), dim3(1024), TAIL_SMEM_WORDS * 4, a_tail, true);
    (void)out_size;
}